// round 8
// baseline (speedup 1.0000x reference)
#include <cuda_runtime.h>
#include <math.h>

#define NPOS 512
#define NALL 1024
#define DIM  512
#define EPSV 1e-5f
#define COSEPS 1e-8f
#define TILE 64
#define DK   32
#define SROW2 33          // float2 per smem row (32 row-pairs + 1 pad)
#define NTHR 1024

// ---------------- device scratch ----------------
__device__ float g_rnorm[NALL];
__device__ float g_t1[NPOS];     // t1 + s3 (pos rows)
__device__ float g_t2[NALL];     // t2 + s3 (all rows)
__device__ float g_deno[NPOS];
__device__ float g_total;
__device__ unsigned g_negdone;
__device__ unsigned g_alldone;

__device__ __forceinline__ float warp_sum(float v) {
#pragma unroll
    for (int o = 16; o; o >>= 1) v += __shfl_xor_sync(0xffffffffu, v, o);
    return v;
}

__device__ __forceinline__ float sp(float x) {   // softplus, stable
    return fmaxf(x, 0.f) + log1pf(expf(-fabsf(x)));
}

// ---------------- kernel 1: per-row norm, t1+s3, t2+s3 (+ scratch init) --------
__global__ void row_kernel(const float* __restrict__ pos,
                           const float* __restrict__ neg,
                           const float* __restrict__ w) {
    int row = blockIdx.x;                       // 0..1023
    int t = threadIdx.x;                        // 128
    if (t == 0) {
        if (row < NPOS) g_deno[row] = 0.f;
        if (row == 0) { g_total = 0.f; g_negdone = 0u; g_alldone = 0u; }
    }
    const float* src = (row < NPOS) ? (pos + row * DIM) : (neg + (row - NPOS) * DIM);
    float4 v  = ((const float4*)src)[t];
    float4 u1 = ((const float4*)w)[t];
    float4 u2 = ((const float4*)(w + DIM))[t];
    float4 u3 = ((const float4*)(w + 2 * DIM))[t];
    float ss = v.x * v.x; ss = fmaf(v.y, v.y, ss); ss = fmaf(v.z, v.z, ss); ss = fmaf(v.w, v.w, ss);
    float d1 = v.x * u1.x; d1 = fmaf(v.y, u1.y, d1); d1 = fmaf(v.z, u1.z, d1); d1 = fmaf(v.w, u1.w, d1);
    float d2 = v.x * u2.x; d2 = fmaf(v.y, u2.y, d2); d2 = fmaf(v.z, u2.z, d2); d2 = fmaf(v.w, u2.w, d2);
    float d3 = v.x * u3.x; d3 = fmaf(v.y, u3.y, d3); d3 = fmaf(v.z, u3.z, d3); d3 = fmaf(v.w, u3.w, d3);
    ss = warp_sum(ss); d1 = warp_sum(d1); d2 = warp_sum(d2); d3 = warp_sum(d3);
    __shared__ float red[4][4];
    int wid = t >> 5, lid = t & 31;
    if (lid == 0) { red[0][wid] = ss; red[1][wid] = d1; red[2][wid] = d2; red[3][wid] = d3; }
    __syncthreads();
    if (t == 0) {
        float S  = red[0][0] + red[0][1] + red[0][2] + red[0][3];
        float D1 = red[1][0] + red[1][1] + red[1][2] + red[1][3];
        float D2 = red[2][0] + red[2][1] + red[2][2] + red[2][3];
        float D3 = red[3][0] + red[3][1] + red[3][2] + red[3][3];
        g_rnorm[row] = 1.f / fmaxf(sqrtf(S), COSEPS);
        g_t2[row] = D2 + D3;                    // t2 + s3
        if (row < NPOS) g_t1[row] = D1 + D3;    // t1 + s3
    }
}

// ---------------- kernel 2: fused pair kernel ----------------
// grid (16, 8): bx<8 -> pos-vs-pos (loss1 + bce), bx>=8 -> pos-vs-neg (deno + bce)
// 1024 threads, scalar 2n x 2m micro-tile; smem [d][rowpair] float2 layout.
//   logit = (t1+s3)[n] + (t2+s3)[m] - 2*sum_d w_d*min(a,b) + bias
__global__ void __launch_bounds__(NTHR, 1) pair_kernel(
    const float* __restrict__ pos, const float* __restrict__ neg,
    const float* __restrict__ w, const float* __restrict__ bptr,
    float* __restrict__ out)
{
    __shared__ float2 sA[DK][SROW2];   // [d][rowpair]
    __shared__ float2 sB[DK][SROW2];
    __shared__ float sW[DK];
    __shared__ float sRed[32];

    const int t  = threadIdx.x;
    const int tx = t & 31;           // m: 2 cols each (cols 2tx, 2tx+1)
    const int ty = t >> 5;           // n: 2 rows each (rows 2ty, 2ty+1), 0..31
    const int n0 = blockIdx.y * TILE;
    const int m0 = blockIdx.x * TILE;
    const bool pos_half = (m0 < NPOS);
    const float* Bsrc = pos_half ? pos : neg;
    const int mrow0 = pos_half ? m0 : (m0 - NPOS);
    const float* w3 = w + 2 * DIM;

    float dotv[2][2], mnv[2][2];
#pragma unroll
    for (int i = 0; i < 2; i++)
#pragma unroll
        for (int j = 0; j < 2; j++) { dotv[i][j] = 0.f; mnv[i][j] = 0.f; }

    // loader mapping: lc = d within chunk (0..31), lp = rowpair (0..31)
    const int lc = t & 31;
    const int lp = t >> 5;

    float pfA0, pfA1, pfB0, pfB1, pfW;
#define LOADC(D0) do {                                               \
    pfA0 = pos [(n0 + 2 * lp)     * DIM + (D0) + lc];                \
    pfA1 = pos [(n0 + 2 * lp + 1) * DIM + (D0) + lc];                \
    pfB0 = Bsrc[(mrow0 + 2 * lp)     * DIM + (D0) + lc];             \
    pfB1 = Bsrc[(mrow0 + 2 * lp + 1) * DIM + (D0) + lc];             \
    if (t < DK) pfW = w3[(D0) + t];                                  \
} while (0)

    LOADC(0);
    for (int c = 0; c < DIM / DK; c++) {
        __syncthreads();
        sA[lc][lp] = make_float2(pfA0, pfA1);
        sB[lc][lp] = make_float2(pfB0, pfB1);
        if (t < DK) sW[t] = pfW;
        __syncthreads();
        if (c < DIM / DK - 1) LOADC((c + 1) * DK);

#pragma unroll 8
        for (int kk = 0; kk < DK; kk++) {
            float2 av = sA[kk][ty];      // broadcast within warp
            float2 bv = sB[kk][tx];      // contiguous 256B, conflict-free
            float a[2] = {av.x, av.y};
            float b[2] = {bv.x, bv.y};
            float wv = sW[kk];
#pragma unroll
            for (int i = 0; i < 2; i++)
#pragma unroll
                for (int j = 0; j < 2; j++) {
                    dotv[i][j] = fmaf(a[i], b[j], dotv[i][j]);
                    mnv[i][j]  = fmaf(fminf(a[i], b[j]), wv, mnv[i][j]); // FMNMX on alu
                }
        }
    }

    // ---- epilogue ----
    int gn[2];
    float rn_n[2], t1v[2], rn_m[2], t2v[2];
#pragma unroll
    for (int i = 0; i < 2; i++) {
        gn[i] = n0 + ty * 2 + i;
        rn_n[i] = g_rnorm[gn[i]];
        t1v[i]  = g_t1[gn[i]];     // includes s3[n]
    }
#pragma unroll
    for (int j = 0; j < 2; j++) {
        int gm = m0 + tx * 2 + j;
        rn_m[j] = g_rnorm[gm];
        t2v[j]  = g_t2[gm];        // includes s3[m]
    }
    float bias = __ldg(bptr);

    float part = 0.f;

    if (!pos_half) {
        // ---- negative half: bce(label 0) + deno ----
        float bce = 0.f, dl[2] = {0.f, 0.f};
#pragma unroll
        for (int i = 0; i < 2; i++) {
#pragma unroll
            for (int j = 0; j < 2; j++) {
                float cc = dotv[i][j] * rn_n[i] * rn_m[j];
                float logit = t1v[i] + t2v[j] - 2.f * mnv[i][j] + bias;
                bce += sp(logit);
                dl[i] += expf(cc);
            }
        }
        // full-warp reduce: lanes cover all 64 m-cols of the tile for row gn[i]
#pragma unroll
        for (int i = 0; i < 2; i++) {
            float v = warp_sum(dl[i]);
            if (tx == 0) atomicAdd(&g_deno[gn[i]], v);
        }
        __threadfence();                       // publish deno before negdone arrive
        part = bce * (1.0f / (float)NALL);
    } else {
        // ---- positive half: wait for deno, then bce(label 1) + contrastive ----
        if (t == 0) {
            while (atomicCAS(&g_negdone, 64u, 64u) != 64u) { __nanosleep(200); }
        }
        __syncthreads();
        __threadfence();
        float dn[2];
#pragma unroll
        for (int i = 0; i < 2; i++) dn[i] = __ldcg(&g_deno[gn[i]]);

        float bce = 0.f, l1 = 0.f;
#pragma unroll
        for (int i = 0; i < 2; i++) {
#pragma unroll
            for (int j = 0; j < 2; j++) {
                float cc = dotv[i][j] * rn_n[i] * rn_m[j];
                float logit = t1v[i] + t2v[j] - 2.f * mnv[i][j] + bias;
                bce += sp(-logit);
                l1 += logf(dn[i] + expf(cc) + EPSV) - cc;  // -log(e^c/(deno+e^c+eps))
            }
        }
        part = bce * (1.0f / (float)NALL) + l1;
    }

    // ---- block reduce + global accumulate + completion protocol ----
    float v = warp_sum(part);
    if ((t & 31) == 0) sRed[t >> 5] = v;
    __syncthreads();
    if (t == 0) {
        float s = 0.f;
#pragma unroll
        for (int k = 0; k < 32; k++) s += sRed[k];
        atomicAdd(&g_total, s);
        __threadfence();
        if (!pos_half) atomicAdd(&g_negdone, 1u);
        unsigned old = atomicAdd(&g_alldone, 1u);
        if (old == 127u) {
            __threadfence();
            out[0] = atomicAdd(&g_total, 0.f);
        }
    }
}

// ---------------- launch ----------------
extern "C" void kernel_launch(void* const* d_in, const int* in_sizes, int n_in,
                              void* d_out, int out_size) {
    const float* pos = (const float*)d_in[0];   // [512,512]
    const float* neg = (const float*)d_in[1];   // [512,512]
    const float* w   = (const float*)d_in[2];   // [1,1536]
    const float* b   = (const float*)d_in[3];   // [1]
    float* out = (float*)d_out;

    row_kernel<<<NALL, 128>>>(pos, neg, w);
    dim3 grid(NALL / TILE, NPOS / TILE);        // (16, 8) — one wave, 128 blocks
    pair_kernel<<<grid, NTHR>>>(pos, neg, w, b, out);
}

// round 9
// speedup vs baseline: 1.1179x; 1.1179x over previous
#include <cuda_runtime.h>
#include <math.h>

#define NPOS 512
#define NALL 1024
#define DIM  512
#define EPSV 1e-5f
#define COSEPS 1e-8f
#define TILE 64
#define DK   64           // k-chunk (doubled), double-buffered
#define SPAD 68           // padded smem row (floats); 272B rows keep float4 16B-aligned
#define NTHR 512
#define NCHUNK (DIM / DK) // 8

// dynamic smem: sA[2][DK][SPAD], sB[2][DK][SPAD], sW[2][DK]
#define SMEM_FLOATS (4 * DK * SPAD + 2 * DK)
#define SMEM_BYTES  (SMEM_FLOATS * 4)

// ---------------- device scratch ----------------
__device__ float g_rnorm[NALL];
__device__ float g_t1[NPOS];     // t1 + s3 (pos rows)
__device__ float g_t2[NALL];     // t2 + s3 (all rows)
__device__ float g_deno[NPOS];
__device__ float g_total;
__device__ unsigned g_negdone;
__device__ unsigned g_alldone;

__device__ __forceinline__ float warp_sum(float v) {
#pragma unroll
    for (int o = 16; o; o >>= 1) v += __shfl_xor_sync(0xffffffffu, v, o);
    return v;
}

__device__ __forceinline__ float sp(float x) {   // softplus, stable
    return fmaxf(x, 0.f) + log1pf(expf(-fabsf(x)));
}

// ---------------- kernel 1: per-row norm, t1+s3, t2+s3 (+ scratch init) --------
__global__ void row_kernel(const float* __restrict__ pos,
                           const float* __restrict__ neg,
                           const float* __restrict__ w) {
    int row = blockIdx.x;                       // 0..1023
    int t = threadIdx.x;                        // 128
    if (t == 0) {
        if (row < NPOS) g_deno[row] = 0.f;
        if (row == 0) { g_total = 0.f; g_negdone = 0u; g_alldone = 0u; }
    }
    const float* src = (row < NPOS) ? (pos + row * DIM) : (neg + (row - NPOS) * DIM);
    float4 v  = ((const float4*)src)[t];
    float4 u1 = ((const float4*)w)[t];
    float4 u2 = ((const float4*)(w + DIM))[t];
    float4 u3 = ((const float4*)(w + 2 * DIM))[t];
    float ss = v.x * v.x; ss = fmaf(v.y, v.y, ss); ss = fmaf(v.z, v.z, ss); ss = fmaf(v.w, v.w, ss);
    float d1 = v.x * u1.x; d1 = fmaf(v.y, u1.y, d1); d1 = fmaf(v.z, u1.z, d1); d1 = fmaf(v.w, u1.w, d1);
    float d2 = v.x * u2.x; d2 = fmaf(v.y, u2.y, d2); d2 = fmaf(v.z, u2.z, d2); d2 = fmaf(v.w, u2.w, d2);
    float d3 = v.x * u3.x; d3 = fmaf(v.y, u3.y, d3); d3 = fmaf(v.z, u3.z, d3); d3 = fmaf(v.w, u3.w, d3);
    ss = warp_sum(ss); d1 = warp_sum(d1); d2 = warp_sum(d2); d3 = warp_sum(d3);
    __shared__ float red[4][4];
    int wid = t >> 5, lid = t & 31;
    if (lid == 0) { red[0][wid] = ss; red[1][wid] = d1; red[2][wid] = d2; red[3][wid] = d3; }
    __syncthreads();
    if (t == 0) {
        float S  = red[0][0] + red[0][1] + red[0][2] + red[0][3];
        float D1 = red[1][0] + red[1][1] + red[1][2] + red[1][3];
        float D2 = red[2][0] + red[2][1] + red[2][2] + red[2][3];
        float D3 = red[3][0] + red[3][1] + red[3][2] + red[3][3];
        g_rnorm[row] = 1.f / fmaxf(sqrtf(S), COSEPS);
        g_t2[row] = D2 + D3;                    // t2 + s3
        if (row < NPOS) g_t1[row] = D1 + D3;    // t1 + s3
    }
}

// ---------------- kernel 2: fused pair kernel ----------------
// grid (16, 8): bx<8 -> pos-vs-pos (loss1 + bce), bx>=8 -> pos-vs-neg (deno + bce)
// 512 threads, scalar 2n x 4m micro-tile; double-buffered DK=64 chunks, 1 sync/chunk.
//   logit = (t1+s3)[n] + (t2+s3)[m] - 2*sum_d w_d*min(a,b) + bias
__global__ void __launch_bounds__(NTHR, 1) pair_kernel(
    const float* __restrict__ pos, const float* __restrict__ neg,
    const float* __restrict__ w, const float* __restrict__ bptr,
    float* __restrict__ out)
{
    extern __shared__ float smem[];
    float (*sA)[DK][SPAD] = (float (*)[DK][SPAD])(smem);
    float (*sB)[DK][SPAD] = (float (*)[DK][SPAD])(smem + 2 * DK * SPAD);
    float (*sW)[DK]       = (float (*)[DK])(smem + 4 * DK * SPAD);
    __shared__ float sRed[16];

    const int t  = threadIdx.x;
    const int tx = t & 15;           // m: 4 cols each
    const int ty = t >> 4;           // n: 2 rows each (0..31)
    const int n0 = blockIdx.y * TILE;
    const int m0 = blockIdx.x * TILE;
    const bool pos_half = (m0 < NPOS);
    const float* Bsrc = pos_half ? pos : neg;
    const int mrow0 = pos_half ? m0 : (m0 - NPOS);
    const float* w3 = w + 2 * DIM;

    float dotv[2][4], mnv[2][4];
#pragma unroll
    for (int i = 0; i < 2; i++)
#pragma unroll
        for (int j = 0; j < 4; j++) { dotv[i][j] = 0.f; mnv[i][j] = 0.f; }

    // loader mapping: lc = d within chunk (0..63), lr = row group (0..7)
    const int lc = t & 63;
    const int lr = t >> 6;

    float pfA[8], pfB[8], pfW;
#define LOADC(D0) do {                                               \
    _Pragma("unroll")                                                \
    for (int q = 0; q < 8; q++) {                                    \
        int r = lr + 8 * q;                                          \
        pfA[q] = pos [(n0 + r)    * DIM + (D0) + lc];                \
        pfB[q] = Bsrc[(mrow0 + r) * DIM + (D0) + lc];                \
    }                                                                \
    if (t < DK) pfW = w3[(D0) + t];                                  \
} while (0)

#define STORC(buf) do {                                              \
    _Pragma("unroll")                                                \
    for (int q = 0; q < 8; q++) {                                    \
        int r = lr + 8 * q;                                          \
        sA[buf][lc][r] = pfA[q];                                     \
        sB[buf][lc][r] = pfB[q];                                     \
    }                                                                \
    if (t < DK) sW[buf][t] = pfW;                                    \
} while (0)

    // prologue: fill buffer 0
    LOADC(0);
    STORC(0);
    __syncthreads();

    for (int c = 0; c < NCHUNK; c++) {
        const int cur = c & 1;
        if (c < NCHUNK - 1) LOADC((c + 1) * DK);   // LDGs land during compute

#pragma unroll 16
        for (int kk = 0; kk < DK; kk++) {
            float2 av = *(const float2*)&sA[cur][kk][ty * 2];
            float4 bv = *(const float4*)&sB[cur][kk][tx * 4];
            float a[2] = {av.x, av.y};
            float b[4] = {bv.x, bv.y, bv.z, bv.w};
            float wv = sW[cur][kk];
#pragma unroll
            for (int i = 0; i < 2; i++)
#pragma unroll
                for (int j = 0; j < 4; j++) {
                    dotv[i][j] = fmaf(a[i], b[j], dotv[i][j]);
                    mnv[i][j]  = fmaf(fminf(a[i], b[j]), wv, mnv[i][j]); // FMNMX on alu
                }
        }

        if (c < NCHUNK - 1) STORC(1 - cur);        // write next buffer
        __syncthreads();                            // one barrier per chunk
    }

    // ---- epilogue ----
    int gn[2];
    float rn_n[2], t1v[2], rn_m[4], t2v[4];
#pragma unroll
    for (int i = 0; i < 2; i++) {
        gn[i] = n0 + ty * 2 + i;
        rn_n[i] = g_rnorm[gn[i]];
        t1v[i]  = g_t1[gn[i]];     // includes s3[n]
    }
#pragma unroll
    for (int j = 0; j < 4; j++) {
        int gm = m0 + tx * 4 + j;
        rn_m[j] = g_rnorm[gm];
        t2v[j]  = g_t2[gm];        // includes s3[m]
    }
    float bias = __ldg(bptr);

    float part = 0.f;

    if (!pos_half) {
        // ---- negative half: bce(label 0) + deno ----
        float bce = 0.f, dl[2] = {0.f, 0.f};
#pragma unroll
        for (int i = 0; i < 2; i++) {
#pragma unroll
            for (int j = 0; j < 4; j++) {
                float cc = dotv[i][j] * rn_n[i] * rn_m[j];
                float logit = t1v[i] + t2v[j] - 2.f * mnv[i][j] + bias;
                bce += sp(logit);
                dl[i] += expf(cc);
            }
        }
        // reduce across the 16 tx-lanes sharing each n-row
#pragma unroll
        for (int i = 0; i < 2; i++) {
            float v = dl[i];
            v += __shfl_xor_sync(0xffffffffu, v, 1);
            v += __shfl_xor_sync(0xffffffffu, v, 2);
            v += __shfl_xor_sync(0xffffffffu, v, 4);
            v += __shfl_xor_sync(0xffffffffu, v, 8);
            if (tx == 0) atomicAdd(&g_deno[gn[i]], v);
        }
        __threadfence();                       // publish deno before negdone arrive
        part = bce * (1.0f / (float)NALL);
    } else {
        // ---- positive half: wait for deno, then bce(label 1) + contrastive ----
        if (t == 0) {
            while (atomicCAS(&g_negdone, 64u, 64u) != 64u) { __nanosleep(200); }
        }
        __syncthreads();
        __threadfence();
        float dn[2];
#pragma unroll
        for (int i = 0; i < 2; i++) dn[i] = __ldcg(&g_deno[gn[i]]);

        float bce = 0.f, l1 = 0.f;
#pragma unroll
        for (int i = 0; i < 2; i++) {
#pragma unroll
            for (int j = 0; j < 4; j++) {
                float cc = dotv[i][j] * rn_n[i] * rn_m[j];
                float logit = t1v[i] + t2v[j] - 2.f * mnv[i][j] + bias;
                bce += sp(-logit);
                l1 += logf(dn[i] + expf(cc) + EPSV) - cc;  // -log(e^c/(deno+e^c+eps))
            }
        }
        part = bce * (1.0f / (float)NALL) + l1;
    }

    // ---- block reduce + global accumulate + completion protocol ----
    float v = warp_sum(part);
    if ((t & 31) == 0) sRed[t >> 5] = v;
    __syncthreads();
    if (t == 0) {
        float s = 0.f;
#pragma unroll
        for (int k = 0; k < 16; k++) s += sRed[k];
        atomicAdd(&g_total, s);
        __threadfence();
        if (!pos_half) atomicAdd(&g_negdone, 1u);
        unsigned old = atomicAdd(&g_alldone, 1u);
        if (old == 127u) {
            __threadfence();
            out[0] = atomicAdd(&g_total, 0.f);
        }
    }
}

// ---------------- launch ----------------
extern "C" void kernel_launch(void* const* d_in, const int* in_sizes, int n_in,
                              void* d_out, int out_size) {
    const float* pos = (const float*)d_in[0];   // [512,512]
    const float* neg = (const float*)d_in[1];   // [512,512]
    const float* w   = (const float*)d_in[2];   // [1,1536]
    const float* b   = (const float*)d_in[3];   // [1]
    float* out = (float*)d_out;

    // opt-in to >48KB dynamic smem (host attribute set; no allocation, capture-safe)
    cudaFuncSetAttribute(pair_kernel,
                         cudaFuncAttributeMaxDynamicSharedMemorySize, SMEM_BYTES);

    row_kernel<<<NALL, 128>>>(pos, neg, w);
    dim3 grid(NALL / TILE, NPOS / TILE);        // (16, 8) — one wave, 128 blocks
    pair_kernel<<<grid, NTHR, SMEM_BYTES>>>(pos, neg, w, b, out);
}